// round 1
// baseline (speedup 1.0000x reference)
#include <cuda_runtime.h>
#include <math.h>

// Problem constants
#define BATCH 2
#define SEQ   2048
#define CDIM  768
#define NHEAD 12
#define HDIM  64
#define MROWS (BATCH*SEQ)     // 4096
#define N3    (3*CDIM)        // 2304
#define BHN   (BATCH*NHEAD)   // 24

// Scratch (device globals; no allocation allowed)
__device__ float g_Q[BATCH*NHEAD*SEQ*HDIM];
__device__ float g_K[BATCH*NHEAD*SEQ*HDIM];
__device__ float g_V[BATCH*NHEAD*SEQ*HDIM];
__device__ float g_attn[BATCH*SEQ*CDIM];

// ---------------------------------------------------------------------------
// Kernel 1: QKV GEMM  [4096,768] @ [768,2304] + bias, scatter into Q/K/V
// 128x128 block tile, BK=8, 256 threads, 8x8 per-thread microtile
// ---------------------------------------------------------------------------
__global__ __launch_bounds__(256) void qkv_gemm_kernel(
    const float* __restrict__ A,      // x [4096,768]
    const float* __restrict__ W,      // [768,2304]
    const float* __restrict__ bias)   // [2304]
{
    __shared__ float As[8][128];
    __shared__ float Bs[8][128];
    const int tid = threadIdx.x;
    const int bn = blockIdx.x;   // 0..17
    const int bm = blockIdx.y;   // 0..31
    const int tx = tid & 15;
    const int ty = tid >> 4;

    float acc[8][8];
    #pragma unroll
    for (int i = 0; i < 8; i++)
        #pragma unroll
        for (int j = 0; j < 8; j++) acc[i][j] = 0.0f;

    const int arow  = tid >> 1;
    const int acol4 = (tid & 1) << 2;
    const int brow  = tid >> 5;
    const int bcol4 = (tid & 31) << 2;

    const float* Ap = A + (bm*128 + arow)*CDIM + acol4;
    const float* Bp = W + brow*N3 + bn*128 + bcol4;

    for (int k0 = 0; k0 < CDIM; k0 += 8) {
        float4 av = *(const float4*)Ap;
        float4 bv = *(const float4*)Bp;
        As[acol4+0][arow] = av.x;
        As[acol4+1][arow] = av.y;
        As[acol4+2][arow] = av.z;
        As[acol4+3][arow] = av.w;
        *(float4*)&Bs[brow][bcol4] = bv;
        __syncthreads();

        #pragma unroll
        for (int k = 0; k < 8; k++) {
            float af[8], bf[8];
            *(float4*)&af[0] = *(const float4*)&As[k][ty*8];
            *(float4*)&af[4] = *(const float4*)&As[k][ty*8+4];
            *(float4*)&bf[0] = *(const float4*)&Bs[k][tx*8];
            *(float4*)&bf[4] = *(const float4*)&Bs[k][tx*8+4];
            #pragma unroll
            for (int i = 0; i < 8; i++)
                #pragma unroll
                for (int j = 0; j < 8; j++)
                    acc[i][j] = fmaf(af[i], bf[j], acc[i][j]);
        }
        __syncthreads();
        Ap += 8;
        Bp += 8*N3;
    }

    // Epilogue: add bias, scatter into [B,H,T,D]
    #pragma unroll
    for (int i = 0; i < 8; i++) {
        const int m = bm*128 + ty*8 + i;
        const int b = m / SEQ;
        const int t = m % SEQ;
        #pragma unroll
        for (int j = 0; j < 8; j++) {
            const int n = bn*128 + tx*8 + j;
            const float v = acc[i][j] + bias[n];
            const int part = n / CDIM;     // 0=q 1=k 2=v
            const int r = n % CDIM;
            const int h = r / HDIM;
            const int d = r % HDIM;
            float* dst = (part == 0) ? g_Q : (part == 1) ? g_K : g_V;
            dst[((b*NHEAD + h)*SEQ + t)*HDIM + d] = v;
        }
    }
}

// ---------------------------------------------------------------------------
// Kernel 2: flash attention, Bq=Bk=64, fp32, online softmax
// grid (32, 24), 256 threads, 4x4 microtiles; padded smem (stride 65)
// ---------------------------------------------------------------------------
__global__ __launch_bounds__(256) void flash_kernel(const int* __restrict__ amask)
{
    extern __shared__ float sm[];
    float* Qs = sm;                 // [64][65]
    float* Ks = sm + 64*65;         // [64][65]  (reused as P)
    float* Vs = sm + 2*64*65;       // [64][65]

    const int qt = blockIdx.x;      // 0..31 query tile
    const int bh = blockIdx.y;      // 0..23
    const int b  = bh / NHEAD;
    const int h  = bh % NHEAD;

    const float* Qg = g_Q + (size_t)bh*SEQ*HDIM + qt*64*HDIM;
    const float* Kg = g_K + (size_t)bh*SEQ*HDIM;
    const float* Vg = g_V + (size_t)bh*SEQ*HDIM;

    const int tid = threadIdx.x;
    const int tx = tid & 15;
    const int ty = tid >> 4;

    // Load Q tile
    for (int i = tid; i < 64*16; i += 256) {
        const int q = i >> 4, dv = (i & 15) << 2;
        float4 v = *(const float4*)(Qg + q*HDIM + dv);
        float* d = &Qs[q*65 + dv];
        d[0] = v.x; d[1] = v.y; d[2] = v.z; d[3] = v.w;
    }
    __syncthreads();

    float m_i[4], l_i[4], o[4][4];
    #pragma unroll
    for (int i = 0; i < 4; i++) {
        m_i[i] = -INFINITY;
        l_i[i] = 0.0f;
        #pragma unroll
        for (int j = 0; j < 4; j++) o[i][j] = 0.0f;
    }

    const float scale = 0.125f;  // 1/sqrt(64)

    for (int kt = 0; kt <= qt; kt++) {
        // Load K,V tile
        for (int i = tid; i < 64*16; i += 256) {
            const int r = i >> 4, dv = (i & 15) << 2;
            float4 kv = *(const float4*)(Kg + (kt*64 + r)*HDIM + dv);
            float4 vv = *(const float4*)(Vg + (kt*64 + r)*HDIM + dv);
            float* kd = &Ks[r*65 + dv];
            kd[0] = kv.x; kd[1] = kv.y; kd[2] = kv.z; kd[3] = kv.w;
            float* vd = &Vs[r*65 + dv];
            vd[0] = vv.x; vd[1] = vv.y; vd[2] = vv.z; vd[3] = vv.w;
        }
        __syncthreads();

        // S = Q @ K^T
        float s[4][4];
        #pragma unroll
        for (int i = 0; i < 4; i++)
            #pragma unroll
            for (int j = 0; j < 4; j++) s[i][j] = 0.0f;

        #pragma unroll 4
        for (int d = 0; d < HDIM; d++) {
            float af[4], bf[4];
            #pragma unroll
            for (int i = 0; i < 4; i++) af[i] = Qs[(ty*4+i)*65 + d];
            #pragma unroll
            for (int j = 0; j < 4; j++) bf[j] = Ks[(tx*4+j)*65 + d];
            #pragma unroll
            for (int i = 0; i < 4; i++)
                #pragma unroll
                for (int j = 0; j < 4; j++)
                    s[i][j] = fmaf(af[i], bf[j], s[i][j]);
        }

        // attention-mask addend per column (setup has all-ones, but be faithful)
        float madd[4];
        #pragma unroll
        for (int j = 0; j < 4; j++) {
            const int kcol = kt*64 + tx*4 + j;
            madd[j] = (amask[b*SEQ + kcol] == 0) ? -INFINITY : 0.0f;
        }

        // online softmax update (rows owned by 16 threads of same ty)
        #pragma unroll
        for (int i = 0; i < 4; i++) {
            const int qrow = qt*64 + ty*4 + i;
            float mx = -INFINITY;
            #pragma unroll
            for (int j = 0; j < 4; j++) {
                const int kcol = kt*64 + tx*4 + j;
                float sv = s[i][j] * scale;
                if (kcol > qrow) sv = -3.402823466e38f;  // finfo.min
                sv += madd[j];
                s[i][j] = sv;
                mx = fmaxf(mx, sv);
            }
            #pragma unroll
            for (int off = 1; off < 16; off <<= 1)
                mx = fmaxf(mx, __shfl_xor_sync(0xffffffffu, mx, off));
            const float mnew = fmaxf(m_i[i], mx);
            const float a = __expf(m_i[i] - mnew);
            float sum = 0.0f;
            #pragma unroll
            for (int j = 0; j < 4; j++) {
                const float p = __expf(s[i][j] - mnew);
                s[i][j] = p;
                sum += p;
            }
            #pragma unroll
            for (int off = 1; off < 16; off <<= 1)
                sum += __shfl_xor_sync(0xffffffffu, sum, off);
            l_i[i] = l_i[i]*a + sum;
            m_i[i] = mnew;
            #pragma unroll
            for (int j = 0; j < 4; j++) o[i][j] *= a;
        }

        __syncthreads();  // all S-reads of Ks done
        // write P into Ks buffer: Ps[q][t]
        #pragma unroll
        for (int i = 0; i < 4; i++)
            #pragma unroll
            for (int j = 0; j < 4; j++)
                Ks[(ty*4+i)*65 + (tx*4+j)] = s[i][j];
        __syncthreads();

        // O += P @ V
        #pragma unroll 4
        for (int t = 0; t < 64; t++) {
            float pf[4], vf[4];
            #pragma unroll
            for (int i = 0; i < 4; i++) pf[i] = Ks[(ty*4+i)*65 + t];
            #pragma unroll
            for (int j = 0; j < 4; j++) vf[j] = Vs[t*65 + tx*4 + j];
            #pragma unroll
            for (int i = 0; i < 4; i++)
                #pragma unroll
                for (int j = 0; j < 4; j++)
                    o[i][j] = fmaf(pf[i], vf[j], o[i][j]);
        }
        __syncthreads();  // before next tile overwrites Ks/Vs
    }

    // write attn_out [B,T,C] with heads merged: out[b][t][h*64+d]
    #pragma unroll
    for (int i = 0; i < 4; i++) {
        const int qrow = qt*64 + ty*4 + i;
        const float inv = 1.0f / l_i[i];
        #pragma unroll
        for (int j = 0; j < 4; j++) {
            g_attn[((size_t)b*SEQ + qrow)*CDIM + h*HDIM + tx*4 + j] = o[i][j] * inv;
        }
    }
}

// ---------------------------------------------------------------------------
// Kernel 3: proj GEMM [4096,768] @ [768,768] + bias -> out
// ---------------------------------------------------------------------------
__global__ __launch_bounds__(256) void proj_gemm_kernel(
    const float* __restrict__ W,      // [768,768]
    const float* __restrict__ bias,   // [768]
    float* __restrict__ out)          // [4096,768]
{
    __shared__ float As[8][128];
    __shared__ float Bs[8][128];
    const int tid = threadIdx.x;
    const int bn = blockIdx.x;   // 0..5
    const int bm = blockIdx.y;   // 0..31
    const int tx = tid & 15;
    const int ty = tid >> 4;

    float acc[8][8];
    #pragma unroll
    for (int i = 0; i < 8; i++)
        #pragma unroll
        for (int j = 0; j < 8; j++) acc[i][j] = 0.0f;

    const int arow  = tid >> 1;
    const int acol4 = (tid & 1) << 2;
    const int brow  = tid >> 5;
    const int bcol4 = (tid & 31) << 2;

    const float* Ap = g_attn + (bm*128 + arow)*CDIM + acol4;
    const float* Bp = W + brow*CDIM + bn*128 + bcol4;

    for (int k0 = 0; k0 < CDIM; k0 += 8) {
        float4 av = *(const float4*)Ap;
        float4 bv = *(const float4*)Bp;
        As[acol4+0][arow] = av.x;
        As[acol4+1][arow] = av.y;
        As[acol4+2][arow] = av.z;
        As[acol4+3][arow] = av.w;
        *(float4*)&Bs[brow][bcol4] = bv;
        __syncthreads();

        #pragma unroll
        for (int k = 0; k < 8; k++) {
            float af[8], bf[8];
            *(float4*)&af[0] = *(const float4*)&As[k][ty*8];
            *(float4*)&af[4] = *(const float4*)&As[k][ty*8+4];
            *(float4*)&bf[0] = *(const float4*)&Bs[k][tx*8];
            *(float4*)&bf[4] = *(const float4*)&Bs[k][tx*8+4];
            #pragma unroll
            for (int i = 0; i < 8; i++)
                #pragma unroll
                for (int j = 0; j < 8; j++)
                    acc[i][j] = fmaf(af[i], bf[j], acc[i][j]);
        }
        __syncthreads();
        Ap += 8;
        Bp += 8*CDIM;
    }

    #pragma unroll
    for (int i = 0; i < 8; i++) {
        const int m = bm*128 + ty*8 + i;
        #pragma unroll
        for (int j = 0; j < 8; j += 4) {
            const int n = bn*128 + tx*8 + j;
            float4 v;
            v.x = acc[i][j+0] + bias[n+0];
            v.y = acc[i][j+1] + bias[n+1];
            v.z = acc[i][j+2] + bias[n+2];
            v.w = acc[i][j+3] + bias[n+3];
            *(float4*)(out + (size_t)m*CDIM + n) = v;
        }
    }
}

// ---------------------------------------------------------------------------
extern "C" void kernel_launch(void* const* d_in, const int* in_sizes, int n_in,
                              void* d_out, int out_size)
{
    (void)in_sizes; (void)n_in; (void)out_size;
    const float* x      = (const float*)d_in[0];
    const int*   amask  = (const int*)d_in[1];
    const float* W_attn = (const float*)d_in[2];
    const float* b_attn = (const float*)d_in[3];
    const float* W_proj = (const float*)d_in[4];
    const float* b_proj = (const float*)d_in[5];
    float* out = (float*)d_out;

    // QKV GEMM
    {
        dim3 grid(N3/128, MROWS/128);   // (18, 32)
        qkv_gemm_kernel<<<grid, 256>>>(x, W_attn, b_attn);
    }

    // Flash attention
    {
        const int smem = 3 * 64 * 65 * (int)sizeof(float);   // 49920 B
        static bool attr_set = false;
        // cudaFuncSetAttribute is idempotent and not a stream op; safe to call
        // unconditionally (host-side only, executes outside captured graph).
        cudaFuncSetAttribute(flash_kernel,
                             cudaFuncAttributeMaxDynamicSharedMemorySize, smem);
        (void)attr_set;
        dim3 grid(SEQ/64, BHN);          // (32, 24)
        flash_kernel<<<grid, 256, smem>>>(amask);
    }

    // Proj GEMM
    {
        dim3 grid(CDIM/128, MROWS/128);  // (6, 32)
        proj_gemm_kernel<<<grid, 256>>>(W_proj, b_proj, out);
    }
}

// round 4
// speedup vs baseline: 3.4505x; 3.4505x over previous
#include <cuda_runtime.h>
#include <math.h>
#include <float.h>

// Problem constants
#define BATCH 2
#define SEQ   2048
#define CDIM  768
#define NHEAD 12
#define HDIM  64
#define MROWS (BATCH*SEQ)     // 4096
#define N3    (3*CDIM)        // 2304
#define BHN   (BATCH*NHEAD)   // 24

// Scratch (device globals; no allocation allowed)
__device__ float g_Q[BATCH*NHEAD*SEQ*HDIM];
__device__ float g_K[BATCH*NHEAD*SEQ*HDIM];
__device__ float g_V[BATCH*NHEAD*SEQ*HDIM];
__device__ float g_attn[BATCH*SEQ*CDIM];

// ---------------------------------------------------------------------------
// helpers
// ---------------------------------------------------------------------------
__device__ __forceinline__ float tf32r(float x) {
    unsigned u;
    asm("cvt.rna.tf32.f32 %0, %1;" : "=r"(u) : "f"(x));
    return __uint_as_float(u);
}

__device__ __forceinline__ void mma_tf32(float* c, const unsigned* a, const unsigned* b) {
    asm volatile(
        "mma.sync.aligned.m16n8k8.row.col.f32.tf32.tf32.f32 "
        "{%0,%1,%2,%3},{%4,%5,%6,%7},{%8,%9},{%0,%1,%2,%3};\n"
        : "+f"(c[0]), "+f"(c[1]), "+f"(c[2]), "+f"(c[3])
        : "r"(a[0]), "r"(a[1]), "r"(a[2]), "r"(a[3]), "r"(b[0]), "r"(b[1]));
}

// ---------------------------------------------------------------------------
// Kernel 1: QKV GEMM  [4096,768] @ [768,2304] + bias, scatter into Q/K/V
// tf32 mma.sync: 128x128 block tile, BK=32, 8 warps, warp 64x32
// ---------------------------------------------------------------------------
__global__ __launch_bounds__(256, 2) void qkv_gemm_kernel(
    const float* __restrict__ A,      // x [4096,768]
    const float* __restrict__ W,      // [768,2304]
    const float* __restrict__ bias)   // [2304]
{
    __shared__ __align__(16) float As[128][36];
    __shared__ __align__(16) float Bs[32][136];

    const int tid = threadIdx.x;
    const int bn = blockIdx.x;   // 0..17
    const int bm = blockIdx.y;   // 0..31
    const int warp = tid >> 5;
    const int lane = tid & 31;
    const int wm = warp >> 2;    // 0..1  -> m offset wm*64
    const int wn = warp & 3;     // 0..3  -> n offset wn*32
    const int lr = lane >> 2;    // 0..7
    const int lc = lane & 3;     // 0..3

    float acc[4][4][4];
    #pragma unroll
    for (int mi = 0; mi < 4; mi++)
        #pragma unroll
        for (int ni = 0; ni < 4; ni++)
            #pragma unroll
            for (int q = 0; q < 4; q++) acc[mi][ni][q] = 0.0f;

    const int arow = tid >> 3;        // 0..31 (per pass of 32 rows)
    const int ac4  = (tid & 7) << 2;  // 0..28
    const int brow = tid >> 5;        // 0..7 (per pass of 8 rows)
    const int bc4  = (tid & 31) << 2; // 0..124

    for (int k0 = 0; k0 < CDIM; k0 += 32) {
        #pragma unroll
        for (int i = 0; i < 4; i++) {
            const int r = arow + i*32;
            float4 v = *(const float4*)(A + (size_t)(bm*128 + r)*CDIM + k0 + ac4);
            float4 t;
            t.x = tf32r(v.x); t.y = tf32r(v.y); t.z = tf32r(v.z); t.w = tf32r(v.w);
            *(float4*)&As[r][ac4] = t;
        }
        #pragma unroll
        for (int i = 0; i < 4; i++) {
            const int r = brow + i*8;
            float4 v = *(const float4*)(W + (size_t)(k0 + r)*N3 + bn*128 + bc4);
            float4 t;
            t.x = tf32r(v.x); t.y = tf32r(v.y); t.z = tf32r(v.z); t.w = tf32r(v.w);
            *(float4*)&Bs[r][bc4] = t;
        }
        __syncthreads();

        #pragma unroll
        for (int ks = 0; ks < 4; ks++) {
            unsigned a[4][4], b[4][2];
            const int kk = ks*8 + lc;
            #pragma unroll
            for (int mi = 0; mi < 4; mi++) {
                const int row = wm*64 + mi*16 + lr;
                a[mi][0] = __float_as_uint(As[row  ][kk  ]);
                a[mi][1] = __float_as_uint(As[row+8][kk  ]);
                a[mi][2] = __float_as_uint(As[row  ][kk+4]);
                a[mi][3] = __float_as_uint(As[row+8][kk+4]);
            }
            #pragma unroll
            for (int ni = 0; ni < 4; ni++) {
                const int coln = wn*32 + ni*8 + lr;
                b[ni][0] = __float_as_uint(Bs[ks*8 + lc    ][coln]);
                b[ni][1] = __float_as_uint(Bs[ks*8 + lc + 4][coln]);
            }
            #pragma unroll
            for (int mi = 0; mi < 4; mi++)
                #pragma unroll
                for (int ni = 0; ni < 4; ni++)
                    mma_tf32(acc[mi][ni], a[mi], b[ni]);
        }
        __syncthreads();
    }

    // Epilogue: bias + scatter into [B,H,T,D], rounded to tf32 for downstream
    #pragma unroll
    for (int mi = 0; mi < 4; mi++) {
        const int r0 = bm*128 + wm*64 + mi*16 + lr;
        const int r1 = r0 + 8;
        #pragma unroll
        for (int ni = 0; ni < 4; ni++) {
            const int n = bn*128 + wn*32 + ni*8 + 2*lc;
            const float b0 = bias[n], b1 = bias[n+1];
            const int part = n / CDIM;
            const int rr = n % CDIM;
            const int h = rr >> 6;
            const int d = rr & 63;
            float* dst = (part == 0) ? g_Q : (part == 1) ? g_K : g_V;

            {
                const int bb = r0 >> 11, t = r0 & 2047;
                float2 v;
                v.x = tf32r(acc[mi][ni][0] + b0);
                v.y = tf32r(acc[mi][ni][1] + b1);
                *(float2*)&dst[(((size_t)bb*NHEAD + h)*SEQ + t)*HDIM + d] = v;
            }
            {
                const int bb = r1 >> 11, t = r1 & 2047;
                float2 v;
                v.x = tf32r(acc[mi][ni][2] + b0);
                v.y = tf32r(acc[mi][ni][3] + b1);
                *(float2*)&dst[(((size_t)bb*NHEAD + h)*SEQ + t)*HDIM + d] = v;
            }
        }
    }
}

// ---------------------------------------------------------------------------
// Kernel 2: flash attention, tf32 mma, Bq=Bk=64, 4 warps
// Static smem only (<48KB): Ks doubles as Q-staging (pre-loop) and P (post-S).
// ---------------------------------------------------------------------------
#define FS 68   // smem row stride (floats): 272B, 16B-aligned

__global__ __launch_bounds__(128) void flash_kernel(const int* __restrict__ amask)
{
    __shared__ __align__(16) float Ks[64*FS];   // Q staging -> K tile -> P tile
    __shared__ __align__(16) float Vs[64*FS];
    __shared__ float msk[64];

    const int qt = blockIdx.x;      // 0..31
    const int bh = blockIdx.y;      // 0..23
    const int b  = bh / NHEAD;
    const int h  = bh % NHEAD;

    const float* Qg = g_Q + (size_t)bh*SEQ*HDIM + qt*64*HDIM;
    const float* Kg = g_K + (size_t)bh*SEQ*HDIM;
    const float* Vg = g_V + (size_t)bh*SEQ*HDIM;

    const int tid = threadIdx.x;
    const int warp = tid >> 5;
    const int lane = tid & 31;
    const int lr = lane >> 2;       // 0..7
    const int lc = lane & 3;        // 0..3

    const int lrow = tid >> 4;      // 0..7 (per pass of 8 rows)
    const int lc4  = (tid & 15) << 2;

    // Stage Q tile in Ks, pull fragments to registers, then release the buffer
    #pragma unroll
    for (int i = 0; i < 8; i++) {
        const int r = lrow + i*8;
        *(float4*)&Ks[r*FS + lc4] = *(const float4*)(Qg + r*HDIM + lc4);
    }
    __syncthreads();

    unsigned qa[8][4];
    #pragma unroll
    for (int ks = 0; ks < 8; ks++) {
        const int row = warp*16 + lr;
        const int kk = ks*8 + lc;
        qa[ks][0] = __float_as_uint(Ks[ row   *FS + kk  ]);
        qa[ks][1] = __float_as_uint(Ks[(row+8)*FS + kk  ]);
        qa[ks][2] = __float_as_uint(Ks[ row   *FS + kk+4]);
        qa[ks][3] = __float_as_uint(Ks[(row+8)*FS + kk+4]);
    }

    float m0 = -INFINITY, m1 = -INFINITY, l0 = 0.0f, l1 = 0.0f;
    float o[8][4];
    #pragma unroll
    for (int nt = 0; nt < 8; nt++)
        #pragma unroll
        for (int q = 0; q < 4; q++) o[nt][q] = 0.0f;

    const int r0g = qt*64 + warp*16 + lr;
    const int r1g = r0g + 8;

    for (int kt = 0; kt <= qt; kt++) {
        __syncthreads();   // prior-iter P/V reads (and Q-frag reads) complete
        #pragma unroll
        for (int i = 0; i < 8; i++) {
            const int r = lrow + i*8;
            *(float4*)&Ks[r*FS + lc4] = *(const float4*)(Kg + (kt*64 + r)*HDIM + lc4);
            *(float4*)&Vs[r*FS + lc4] = *(const float4*)(Vg + (kt*64 + r)*HDIM + lc4);
        }
        if (tid < 64)
            msk[tid] = (amask[b*SEQ + kt*64 + tid] == 0) ? -INFINITY : 0.0f;
        __syncthreads();

        // S = Q @ K^T
        float s[8][4];
        #pragma unroll
        for (int nt = 0; nt < 8; nt++)
            #pragma unroll
            for (int q = 0; q < 4; q++) s[nt][q] = 0.0f;

        #pragma unroll
        for (int ks = 0; ks < 8; ks++) {
            #pragma unroll
            for (int nt = 0; nt < 8; nt++) {
                unsigned kb[2];
                kb[0] = __float_as_uint(Ks[(nt*8 + lr)*FS + ks*8 + lc    ]);
                kb[1] = __float_as_uint(Ks[(nt*8 + lr)*FS + ks*8 + lc + 4]);
                mma_tf32(s[nt], qa[ks], kb);
            }
        }

        // scale + causal + attn-mask, track row max
        float mx0 = -INFINITY, mx1 = -INFINITY;
        #pragma unroll
        for (int nt = 0; nt < 8; nt++) {
            #pragma unroll
            for (int cc = 0; cc < 2; cc++) {
                const int lcol = nt*8 + 2*lc + cc;
                const int col = kt*64 + lcol;
                const float ma = msk[lcol];
                float v0 = s[nt][cc  ]*0.125f + ma;
                float v1 = s[nt][cc+2]*0.125f + ma;
                if (col > r0g) v0 = -3.402823466e38f;
                if (col > r1g) v1 = -3.402823466e38f;
                s[nt][cc  ] = v0;
                s[nt][cc+2] = v1;
                mx0 = fmaxf(mx0, v0);
                mx1 = fmaxf(mx1, v1);
            }
        }
        mx0 = fmaxf(mx0, __shfl_xor_sync(0xffffffffu, mx0, 1));
        mx0 = fmaxf(mx0, __shfl_xor_sync(0xffffffffu, mx0, 2));
        mx1 = fmaxf(mx1, __shfl_xor_sync(0xffffffffu, mx1, 1));
        mx1 = fmaxf(mx1, __shfl_xor_sync(0xffffffffu, mx1, 2));

        const float mn0 = fmaxf(m0, mx0);
        const float mn1 = fmaxf(m1, mx1);
        const float al0 = __expf(m0 - mn0);
        const float al1 = __expf(m1 - mn1);
        float sum0 = 0.0f, sum1 = 0.0f;
        #pragma unroll
        for (int nt = 0; nt < 8; nt++) {
            #pragma unroll
            for (int cc = 0; cc < 2; cc++) {
                const float p0 = __expf(s[nt][cc  ] - mn0);
                const float p1 = __expf(s[nt][cc+2] - mn1);
                s[nt][cc  ] = p0;
                s[nt][cc+2] = p1;
                sum0 += p0;
                sum1 += p1;
            }
        }
        sum0 += __shfl_xor_sync(0xffffffffu, sum0, 1);
        sum0 += __shfl_xor_sync(0xffffffffu, sum0, 2);
        sum1 += __shfl_xor_sync(0xffffffffu, sum1, 1);
        sum1 += __shfl_xor_sync(0xffffffffu, sum1, 2);
        l0 = l0*al0 + sum0;  m0 = mn0;
        l1 = l1*al1 + sum1;  m1 = mn1;
        #pragma unroll
        for (int nt = 0; nt < 8; nt++) {
            o[nt][0] *= al0; o[nt][1] *= al0;
            o[nt][2] *= al1; o[nt][3] *= al1;
        }

        // All warps finished reading K; P overwrites the Ks buffer.
        __syncthreads();
        #pragma unroll
        for (int nt = 0; nt < 8; nt++) {
            float2 p01, p23;
            p01.x = tf32r(s[nt][0]); p01.y = tf32r(s[nt][1]);
            p23.x = tf32r(s[nt][2]); p23.y = tf32r(s[nt][3]);
            *(float2*)&Ks[(warp*16 + lr    )*FS + nt*8 + 2*lc] = p01;
            *(float2*)&Ks[(warp*16 + lr + 8)*FS + nt*8 + 2*lc] = p23;
        }
        __syncwarp();   // P rows are warp-private; only this warp reads them

        // O += P @ V
        #pragma unroll
        for (int ks = 0; ks < 8; ks++) {
            unsigned pa[4];
            const int row = warp*16 + lr;
            const int kk = ks*8 + lc;
            pa[0] = __float_as_uint(Ks[ row   *FS + kk  ]);
            pa[1] = __float_as_uint(Ks[(row+8)*FS + kk  ]);
            pa[2] = __float_as_uint(Ks[ row   *FS + kk+4]);
            pa[3] = __float_as_uint(Ks[(row+8)*FS + kk+4]);
            #pragma unroll
            for (int nt = 0; nt < 8; nt++) {
                unsigned vb[2];
                vb[0] = __float_as_uint(Vs[(ks*8 + lc    )*FS + nt*8 + lr]);
                vb[1] = __float_as_uint(Vs[(ks*8 + lc + 4)*FS + nt*8 + lr]);
                mma_tf32(o[nt], pa, vb);
            }
        }
    }

    // epilogue: normalize, round to tf32 for proj, write [B,T,C]
    const float inv0 = 1.0f / l0;
    const float inv1 = 1.0f / l1;
    #pragma unroll
    for (int nt = 0; nt < 8; nt++) {
        const int col = h*HDIM + nt*8 + 2*lc;
        float2 v0, v1;
        v0.x = tf32r(o[nt][0]*inv0); v0.y = tf32r(o[nt][1]*inv0);
        v1.x = tf32r(o[nt][2]*inv1); v1.y = tf32r(o[nt][3]*inv1);
        *(float2*)&g_attn[((size_t)b*SEQ + r0g)*CDIM + col] = v0;
        *(float2*)&g_attn[((size_t)b*SEQ + r1g)*CDIM + col] = v1;
    }
}

// ---------------------------------------------------------------------------
// Kernel 3: proj GEMM [4096,768] @ [768,768] + bias -> out (fp32 out)
// ---------------------------------------------------------------------------
__global__ __launch_bounds__(256, 2) void proj_gemm_kernel(
    const float* __restrict__ W,      // [768,768]
    const float* __restrict__ bias,   // [768]
    float* __restrict__ out)          // [4096,768]
{
    __shared__ __align__(16) float As[128][36];
    __shared__ __align__(16) float Bs[32][136];

    const int tid = threadIdx.x;
    const int bn = blockIdx.x;   // 0..5
    const int bm = blockIdx.y;   // 0..31
    const int warp = tid >> 5;
    const int lane = tid & 31;
    const int wm = warp >> 2;
    const int wn = warp & 3;
    const int lr = lane >> 2;
    const int lc = lane & 3;

    float acc[4][4][4];
    #pragma unroll
    for (int mi = 0; mi < 4; mi++)
        #pragma unroll
        for (int ni = 0; ni < 4; ni++)
            #pragma unroll
            for (int q = 0; q < 4; q++) acc[mi][ni][q] = 0.0f;

    const int arow = tid >> 3;
    const int ac4  = (tid & 7) << 2;
    const int brow = tid >> 5;
    const int bc4  = (tid & 31) << 2;

    for (int k0 = 0; k0 < CDIM; k0 += 32) {
        #pragma unroll
        for (int i = 0; i < 4; i++) {
            const int r = arow + i*32;
            // g_attn already tf32-rounded by flash epilogue
            *(float4*)&As[r][ac4] =
                *(const float4*)(g_attn + (size_t)(bm*128 + r)*CDIM + k0 + ac4);
        }
        #pragma unroll
        for (int i = 0; i < 4; i++) {
            const int r = brow + i*8;
            float4 v = *(const float4*)(W + (size_t)(k0 + r)*CDIM + bn*128 + bc4);
            float4 t;
            t.x = tf32r(v.x); t.y = tf32r(v.y); t.z = tf32r(v.z); t.w = tf32r(v.w);
            *(float4*)&Bs[r][bc4] = t;
        }
        __syncthreads();

        #pragma unroll
        for (int ks = 0; ks < 4; ks++) {
            unsigned a[4][4], b[4][2];
            const int kk = ks*8 + lc;
            #pragma unroll
            for (int mi = 0; mi < 4; mi++) {
                const int row = wm*64 + mi*16 + lr;
                a[mi][0] = __float_as_uint(As[row  ][kk  ]);
                a[mi][1] = __float_as_uint(As[row+8][kk  ]);
                a[mi][2] = __float_as_uint(As[row  ][kk+4]);
                a[mi][3] = __float_as_uint(As[row+8][kk+4]);
            }
            #pragma unroll
            for (int ni = 0; ni < 4; ni++) {
                const int coln = wn*32 + ni*8 + lr;
                b[ni][0] = __float_as_uint(Bs[ks*8 + lc    ][coln]);
                b[ni][1] = __float_as_uint(Bs[ks*8 + lc + 4][coln]);
            }
            #pragma unroll
            for (int mi = 0; mi < 4; mi++)
                #pragma unroll
                for (int ni = 0; ni < 4; ni++)
                    mma_tf32(acc[mi][ni], a[mi], b[ni]);
        }
        __syncthreads();
    }

    #pragma unroll
    for (int mi = 0; mi < 4; mi++) {
        const int r0 = bm*128 + wm*64 + mi*16 + lr;
        const int r1 = r0 + 8;
        #pragma unroll
        for (int ni = 0; ni < 4; ni++) {
            const int n = bn*128 + wn*32 + ni*8 + 2*lc;
            const float b0 = bias[n], b1 = bias[n+1];
            float2 v0, v1;
            v0.x = acc[mi][ni][0] + b0; v0.y = acc[mi][ni][1] + b1;
            v1.x = acc[mi][ni][2] + b0; v1.y = acc[mi][ni][3] + b1;
            *(float2*)&out[(size_t)r0*CDIM + n] = v0;
            *(float2*)&out[(size_t)r1*CDIM + n] = v1;
        }
    }
}

// ---------------------------------------------------------------------------
extern "C" void kernel_launch(void* const* d_in, const int* in_sizes, int n_in,
                              void* d_out, int out_size)
{
    (void)in_sizes; (void)n_in; (void)out_size;
    const float* x      = (const float*)d_in[0];
    const int*   amask  = (const int*)d_in[1];
    const float* W_attn = (const float*)d_in[2];
    const float* b_attn = (const float*)d_in[3];
    const float* W_proj = (const float*)d_in[4];
    const float* b_proj = (const float*)d_in[5];
    float* out = (float*)d_out;

    {
        dim3 grid(N3/128, MROWS/128);   // (18, 32)
        qkv_gemm_kernel<<<grid, 256>>>(x, W_attn, b_attn);
    }
    {
        dim3 grid(SEQ/64, BHN);          // (32, 24)
        flash_kernel<<<grid, 128>>>(amask);
    }
    {
        dim3 grid(CDIM/128, MROWS/128);  // (6, 32)
        proj_gemm_kernel<<<grid, 256>>>(W_proj, b_proj, out);
    }
}